// round 13
// baseline (speedup 1.0000x reference)
#include <cuda_runtime.h>
#include <cuda_bf16.h>
#include <cstdint>
#include <math.h>

// ---------------- problem constants ----------------
#define MAXN   100000
#define MROUND 100096      // MAXN rounded up to 128-row tiles
#define MAXE   1600000
#define DIM    128
#define HID    256

// ---------------- scratch (static device memory; no allocation) ----------------
__device__ __align__(128) float g_xi  [(size_t)MROUND * DIM];
__device__ __align__(128) float g_gi  [(size_t)MROUND * 3 * DIM];
__device__ __align__(128) float g_gh  [(size_t)MROUND * 3 * DIM];
__device__ __align__(128) float g_stats[1024];
__device__ __align__(128) __nv_bfloat16 g_xh [(size_t)MROUND * DIM];
__device__ __align__(128) __nv_bfloat16 g_xl [(size_t)MROUND * DIM];
__device__ __align__(128) __nv_bfloat16 g_ash[(size_t)MROUND * DIM];
__device__ __align__(128) __nv_bfloat16 g_asl[(size_t)MROUND * DIM];
__device__ __align__(128) __nv_bfloat16 g_amh[(size_t)MROUND * DIM];
__device__ __align__(128) __nv_bfloat16 g_aml[(size_t)MROUND * DIM];
__device__ __align__(128) __nv_bfloat16 g_rnh[(size_t)MROUND * DIM];
__device__ __align__(128) __nv_bfloat16 g_rnl[(size_t)MROUND * DIM];
__device__ __align__(128) __nv_bfloat16 g_hh [(size_t)MROUND * DIM];
__device__ __align__(128) __nv_bfloat16 g_hl [(size_t)MROUND * DIM];
__device__ __align__(128) __nv_bfloat16 g_t1h[(size_t)MROUND * HID];
__device__ __align__(128) __nv_bfloat16 g_t1l[(size_t)MROUND * HID];
__device__ __align__(128) __nv_bfloat16 g_waffh[128*128], g_waffl[128*128];
__device__ __align__(128) __nv_bfloat16 g_wihh [384*128], g_wihl [384*128];
__device__ __align__(128) __nv_bfloat16 g_whhh [384*128], g_whhl [384*128];
__device__ __align__(128) __nv_bfloat16 g_wmh  [128*256], g_wml  [128*256];
__device__ __align__(128) __nv_bfloat16 g_w1h  [256*128], g_w1l  [256*128];
__device__ __align__(128) __nv_bfloat16 g_w2h  [128*256], g_w2l  [128*256];
__device__ __align__(128) int g_deg [MAXN];
__device__ __align__(128) int g_off [MAXN];
__device__ __align__(128) int g_cur [MAXN];
__device__ __align__(128) int g_part[1024];
__device__ __align__(128) int g_ssrc[MAXE];

// ================= helpers =================
__device__ __forceinline__ uint32_t smem_u32(const void* p) {
    uint32_t a;
    asm("{ .reg .u64 t; cvta.to.shared.u64 t, %1; cvt.u32.u64 %0, t; }" : "=r"(a) : "l"(p));
    return a;
}
__device__ __forceinline__ void ldsm_x4(uint32_t& r0, uint32_t& r1, uint32_t& r2, uint32_t& r3,
                                        uint32_t addr) {
    asm volatile("ldmatrix.sync.aligned.m8n8.x4.shared.b16 {%0,%1,%2,%3}, [%4];"
                 : "=r"(r0), "=r"(r1), "=r"(r2), "=r"(r3) : "r"(addr));
}
__device__ __forceinline__ void mma_bf16(float* c, const uint32_t* a, uint32_t b0, uint32_t b1) {
    asm volatile(
        "mma.sync.aligned.m16n8k16.row.col.f32.bf16.bf16.f32 "
        "{%0,%1,%2,%3}, {%4,%5,%6,%7}, {%8,%9}, {%0,%1,%2,%3};"
        : "+f"(c[0]), "+f"(c[1]), "+f"(c[2]), "+f"(c[3])
        : "r"(a[0]), "r"(a[1]), "r"(a[2]), "r"(a[3]), "r"(b0), "r"(b1));
}
__device__ __forceinline__ void split2(float vx, float vy, uint32_t& hi, uint32_t& lo) {
    __nv_bfloat162 h = __floats2bfloat162_rn(vx, vy);
    float rx = vx - __bfloat162float(h.x);
    float ry = vy - __bfloat162float(h.y);
    __nv_bfloat162 l = __floats2bfloat162_rn(rx, ry);
    hi = *reinterpret_cast<const uint32_t*>(&h);
    lo = *reinterpret_cast<const uint32_t*>(&l);
}

// ---------------- smem layout ----------------
#define SROW      136
#define ATILE_B   (128 * SROW * 2)
#define WTILE_B   (64  * SROW * 2)
#define OFF_AHI   0
#define OFF_ALO   (ATILE_B)
#define OFF_WHI   (2 * ATILE_B)
#define OFF_WLO   (2 * ATILE_B + WTILE_B)
#define TCG_SMEM  (2 * ATILE_B + 2 * WTILE_B)   // 104448 -> 2 CTAs/SM
#define TCG_BNS   (TCG_SMEM + 1024)             // +256 floats of BN accumulators

// ================= GEMM core building blocks (shared by both kernels) =================
struct MmaCtx {
    uint32_t sb;
    uint32_t aRowPart, bRowPart;
    int tid, wid, lane, bm, wm, wn, qr, qc;
};
__device__ __forceinline__ MmaCtx make_ctx(const char* smem) {
    MmaCtx c;
    c.sb   = smem_u32(smem);
    c.tid  = threadIdx.x;
    c.wid  = c.tid >> 5;
    c.lane = c.tid & 31;
    c.bm   = blockIdx.x * 128;
    c.wm   = (c.wid >> 1) * 32;
    c.wn   = (c.wid & 1) * 32;
    const int g  = c.lane >> 3;
    const int lr = c.lane & 7;
    c.aRowPart = (uint32_t)((c.wm + (g & 1) * 8 + lr) * SROW + (g >> 1) * 8);
    c.bRowPart = (uint32_t)((c.wn + (g >> 1) * 8 + lr) * SROW + (g & 1) * 8);
    c.qr = c.lane >> 2;
    c.qc = (c.lane & 3) * 2;
    return c;
}
__device__ __forceinline__ void load_A(char* smem, const MmaCtx& c,
                                       const __nv_bfloat16* ah, const __nv_bfloat16* al, int lda) {
#pragma unroll 4
    for (int it = c.tid; it < 2048; it += 256) {
        const int r = it >> 4;
        const int cc = (it & 15) * 8;
        const uint32_t off = (uint32_t)(r * SROW + cc) * 2;
        const size_t ga = (size_t)(c.bm + r) * lda + cc;
        *reinterpret_cast<uint4*>(smem + OFF_AHI + off) = *reinterpret_cast<const uint4*>(ah + ga);
        *reinterpret_cast<uint4*>(smem + OFF_ALO + off) = *reinterpret_cast<const uint4*>(al + ga);
    }
}
__device__ __forceinline__ void load_W(char* smem, const MmaCtx& c,
                                       const __nv_bfloat16* wh, const __nv_bfloat16* wl,
                                       int ldw, int rowbase, int kofs) {
#pragma unroll 2
    for (int it = c.tid; it < 1024; it += 256) {
        const int r = it >> 4;
        const int cc = (it & 15) * 8;
        const uint32_t off = (uint32_t)(r * SROW + cc) * 2;
        const size_t gw = (size_t)(rowbase + r) * ldw + kofs + cc;
        *reinterpret_cast<uint4*>(smem + OFF_WHI + off) = *reinterpret_cast<const uint4*>(wh + gw);
        *reinterpret_cast<uint4*>(smem + OFF_WLO + off) = *reinterpret_cast<const uint4*>(wl + gw);
    }
}
__device__ __forceinline__ void mma_chunk(const MmaCtx& c, float acc[2][4][4]) {
#pragma unroll
    for (int ks = 0; ks < 8; ks++) {
        const uint32_t kk = ks * 16;
        uint32_t ah_[2][4], al_[2][4];
        uint32_t bh_[4][2], bl_[4][2];
#pragma unroll
        for (int i = 0; i < 2; i++) {
            const uint32_t ao = (c.aRowPart + (uint32_t)(i * 16) * SROW + kk) * 2;
            ldsm_x4(ah_[i][0], ah_[i][1], ah_[i][2], ah_[i][3], c.sb + OFF_AHI + ao);
            ldsm_x4(al_[i][0], al_[i][1], al_[i][2], al_[i][3], c.sb + OFF_ALO + ao);
        }
        {
            const uint32_t bo0 = (c.bRowPart + kk) * 2;
            const uint32_t bo1 = (c.bRowPart + (uint32_t)(16 * SROW) + kk) * 2;
            ldsm_x4(bh_[0][0], bh_[0][1], bh_[1][0], bh_[1][1], c.sb + OFF_WHI + bo0);
            ldsm_x4(bh_[2][0], bh_[2][1], bh_[3][0], bh_[3][1], c.sb + OFF_WHI + bo1);
            ldsm_x4(bl_[0][0], bl_[0][1], bl_[1][0], bl_[1][1], c.sb + OFF_WLO + bo0);
            ldsm_x4(bl_[2][0], bl_[2][1], bl_[3][0], bl_[3][1], c.sb + OFF_WLO + bo1);
        }
#pragma unroll
        for (int i = 0; i < 2; i++)
#pragma unroll
            for (int j = 0; j < 4; j++) {
                mma_bf16(acc[i][j], ah_[i], bh_[j][0], bh_[j][1]);
                mma_bf16(acc[i][j], ah_[i], bl_[j][0], bl_[j][1]);
                mma_bf16(acc[i][j], al_[i], bh_[j][0], bh_[j][1]);
            }
    }
}

// ---------------- generic tensor GEMM (split-bf16, fp32 acc) ----------------
template<bool RELU, bool BIAS, bool EXTRA, bool OUTHL, bool BNS>
__global__ __launch_bounds__(256, 2)
void tc_gemm(const __nv_bfloat16* __restrict__ a0h, const __nv_bfloat16* __restrict__ a0l,
             const __nv_bfloat16* __restrict__ a1h, const __nv_bfloat16* __restrict__ a1l,
             int lda,
             const __nv_bfloat16* __restrict__ wh, const __nv_bfloat16* __restrict__ wl,
             int ldw,
             const float* __restrict__ bias, const float* __restrict__ extra,
             const float* __restrict__ epsp,
             float* __restrict__ Cf,
             __nv_bfloat16* __restrict__ Chh, __nv_bfloat16* __restrict__ Cll,
             int ldc, int M, int KC, int NYT)
{
    extern __shared__ char smem[];
    const MmaCtx c = make_ctx(smem);
    float* sacc = reinterpret_cast<float*>(smem + TCG_SMEM);
    if (BNS && c.tid < 256) sacc[c.tid] = 0.f;

    const float epsv = EXTRA ? __ldg(epsp) : 0.f;

    for (int ny = 0; ny < NYT; ny++) {
        float acc[2][4][4];
#pragma unroll
        for (int i = 0; i < 2; i++)
#pragma unroll
            for (int j = 0; j < 4; j++)
#pragma unroll
                for (int f = 0; f < 4; f++) acc[i][j][f] = 0.f;

        for (int kc = 0; kc < KC; kc++) {
            if (ny || kc) __syncthreads();
            if (KC > 1 || ny == 0)
                load_A(smem, c, kc ? a1h : a0h, kc ? a1l : a0l, lda);
            load_W(smem, c, wh, wl, ldw, ny * 64, kc * 128);
            __syncthreads();
            mma_chunk(c, acc);
        }

        // ---- epilogue (j-outer so BN partial sums reduce in registers) ----
#pragma unroll
        for (int j = 0; j < 4; j++) {
            const int col = ny * 64 + c.wn + j * 8 + c.qc;
            float bsx = 0.f, bsy = 0.f, bqx = 0.f, bqy = 0.f;
#pragma unroll
            for (int i = 0; i < 2; i++) {
#pragma unroll
                for (int half = 0; half < 2; half++) {
                    const int rr = c.bm + c.wm + i * 16 + c.qr + half * 8;
                    if (rr < M) {
                        float vx = acc[i][j][half * 2 + 0];
                        float vy = acc[i][j][half * 2 + 1];
                        if (BIAS) {
                            const float2 b2 = *reinterpret_cast<const float2*>(bias + col);
                            vx += b2.x; vy += b2.y;
                        }
                        if (EXTRA) {
                            const float2 e2 = *reinterpret_cast<const float2*>(extra + (size_t)rr * ldc + col);
                            vx = fmaf(epsv, e2.x, vx); vy = fmaf(epsv, e2.y, vy);
                        }
                        if (RELU) { vx = fmaxf(vx, 0.f); vy = fmaxf(vy, 0.f); }
                        if (OUTHL) {
                            uint32_t hi, lo;
                            split2(vx, vy, hi, lo);
                            *reinterpret_cast<uint32_t*>(Chh + (size_t)rr * ldc + col) = hi;
                            *reinterpret_cast<uint32_t*>(Cll + (size_t)rr * ldc + col) = lo;
                        } else {
                            *reinterpret_cast<float2*>(Cf + (size_t)rr * ldc + col) = make_float2(vx, vy);
                        }
                        if (BNS) {
                            bsx += vx; bsy += vy;
                            bqx = fmaf(vx, vx, bqx); bqy = fmaf(vy, vy, bqy);
                        }
                    }
                }
            }
            if (BNS) {
                atomicAdd(&sacc[col],           bsx);
                atomicAdd(&sacc[col + 1],       bsy);
                atomicAdd(&sacc[128 + col],     bqx);
                atomicAdd(&sacc[128 + col + 1], bqy);
            }
        }
    }

    if (BNS) {
        __syncthreads();
        if (c.tid < 128) {
            atomicAdd(&g_stats[c.tid],       sacc[c.tid]);
            atomicAdd(&g_stats[128 + c.tid], sacc[128 + c.tid]);
        }
    }
}

// ---------------- merged xi + gh GEMM (shared resident A = x split) ----------------
// subtiles 0-1: xi = x @ W_aff^T + b_aff (fp32, ldc=128)
// subtiles 2-7: gh = x @ W_hh^T  + b_hh  (fp32, ldc=384)
__global__ __launch_bounds__(256, 2)
void tc_gemm_xigh(const __nv_bfloat16* __restrict__ xh, const __nv_bfloat16* __restrict__ xl,
                  const __nv_bfloat16* __restrict__ waffh, const __nv_bfloat16* __restrict__ waffl,
                  const __nv_bfloat16* __restrict__ whhh,  const __nv_bfloat16* __restrict__ whhl,
                  const float* __restrict__ b_aff, const float* __restrict__ b_hh,
                  float* __restrict__ xi, float* __restrict__ gh, int M)
{
    extern __shared__ char smem[];
    const MmaCtx c = make_ctx(smem);

    for (int ny = 0; ny < 8; ny++) {
        const bool isXi = (ny < 2);
        const int  wrow = isXi ? ny * 64 : (ny - 2) * 64;

        float acc[2][4][4];
#pragma unroll
        for (int i = 0; i < 2; i++)
#pragma unroll
            for (int j = 0; j < 4; j++)
#pragma unroll
                for (int f = 0; f < 4; f++) acc[i][j][f] = 0.f;

        if (ny) __syncthreads();
        if (ny == 0) load_A(smem, c, xh, xl, DIM);
        load_W(smem, c, isXi ? waffh : whhh, isXi ? waffl : whhl, DIM, wrow, 0);
        __syncthreads();
        mma_chunk(c, acc);

        const float* bias = isXi ? b_aff : b_hh;
        float* Cf  = isXi ? xi : gh;
        const int  ldc = isXi ? 128 : 384;
#pragma unroll
        for (int j = 0; j < 4; j++) {
            const int col = wrow + c.wn + j * 8 + c.qc;
#pragma unroll
            for (int i = 0; i < 2; i++) {
#pragma unroll
                for (int half = 0; half < 2; half++) {
                    const int rr = c.bm + c.wm + i * 16 + c.qr + half * 8;
                    if (rr < M) {
                        const float2 b2 = *reinterpret_cast<const float2*>(bias + col);
                        *reinterpret_cast<float2*>(Cf + (size_t)rr * ldc + col) =
                            make_float2(acc[i][j][half * 2 + 0] + b2.x,
                                        acc[i][j][half * 2 + 1] + b2.y);
                    }
                }
            }
        }
    }
}

// ================= merged split kernel: all fp32 -> bf16 hi/lo regions =================
struct SplitJobs {
    const float* src[7];
    __nv_bfloat16* dh[7];
    __nv_bfloat16* dl[7];
    int off[8];
};

__global__ void k_split_all(SplitJobs jobs) {
    const int i = blockIdx.x * blockDim.x + threadIdx.x;
    if (i >= jobs.off[7]) return;
    int r = 0;
#pragma unroll
    for (int k = 1; k < 7; k++) r += (i >= jobs.off[k]);
    const int li = i - jobs.off[r];
    const float4 v = *reinterpret_cast<const float4*>(jobs.src[r] + (size_t)li * 4);
    uint32_t h0, l0, h1, l1;
    split2(v.x, v.y, h0, l0);
    split2(v.z, v.w, h1, l1);
    *reinterpret_cast<uint2*>(jobs.dh[r] + (size_t)li * 4) = make_uint2(h0, h1);
    *reinterpret_cast<uint2*>(jobs.dl[r] + (size_t)li * 4) = make_uint2(l0, l1);
}

// ================= CSR build =================
__global__ void k_zero(int M) {
    int i = blockIdx.x * blockDim.x + threadIdx.x;
    if (i < M) g_deg[i] = 0;
    if (i < 1024) g_stats[i] = 0.f;
}
__global__ void k_hist(const int* __restrict__ edges, int E) {
    int i = blockIdx.x * blockDim.x + threadIdx.x;
    if (i < E) atomicAdd(&g_deg[__ldg(edges + E + i)], 1);
}
__global__ void k_scan1(int M) {
    __shared__ int s[512];
    const int tid = threadIdx.x;
    const int i = blockIdx.x * 512 + tid;
    const int v = (i < M) ? g_deg[i] : 0;
    s[tid] = v;
    __syncthreads();
#pragma unroll
    for (int d = 1; d < 512; d <<= 1) {
        int u = (tid >= d) ? s[tid - d] : 0;
        __syncthreads();
        s[tid] += u;
        __syncthreads();
    }
    if (i < M) g_off[i] = s[tid] - v;
    if (tid == 511) g_part[blockIdx.x] = s[511];
}
__global__ void k_scan2(int nblk) {
    __shared__ int s[1024];
    const int t = threadIdx.x;
    const int v = (t < nblk) ? g_part[t] : 0;
    s[t] = v;
    __syncthreads();
#pragma unroll
    for (int d = 1; d < 1024; d <<= 1) {
        int u = (t >= d) ? s[t - d] : 0;
        __syncthreads();
        s[t] += u;
        __syncthreads();
    }
    if (t < nblk) g_part[t] = s[t] - v;
}
__global__ void k_scan3(int M) {
    int i = blockIdx.x * blockDim.x + threadIdx.x;
    if (i < M) {
        int o = g_off[i] + g_part[i >> 9];
        g_off[i] = o;
        g_cur[i] = o;
    }
}
__global__ void k_place(const int* __restrict__ edges, int E) {
    int i = blockIdx.x * blockDim.x + threadIdx.x;
    if (i < E) {
        const int s = __ldg(edges + i);
        const int d = __ldg(edges + E + i);
        const int pos = atomicAdd(&g_cur[d], 1);
        g_ssrc[pos] = s;
    }
}

// ================= aggregation: warp per node, 2-edge unroll, no atomics =================
__global__ __launch_bounds__(256)
void k_aggregate(const float* __restrict__ x, int M)
{
    const int w = blockIdx.x * 8 + (threadIdx.x >> 5);
    const int lane = threadIdx.x & 31;
    if (w >= M) return;
    const int beg = g_off[w];
    const int deg = g_deg[w];
    const int co = lane * 4;

    float4 sum = make_float4(0.f, 0.f, 0.f, 0.f);
    float4 mx  = make_float4(-INFINITY, -INFINITY, -INFINITY, -INFINITY);

    int e = 0;
    for (; e + 2 <= deg; e += 2) {
        const int s0 = __ldg(g_ssrc + beg + e);
        const int s1 = __ldg(g_ssrc + beg + e + 1);
        const float4 a0 = *reinterpret_cast<const float4*>(x    + (size_t)s0 * DIM + co);
        const float4 m0 = *reinterpret_cast<const float4*>(g_xi + (size_t)s0 * DIM + co);
        const float4 a1 = *reinterpret_cast<const float4*>(x    + (size_t)s1 * DIM + co);
        const float4 m1 = *reinterpret_cast<const float4*>(g_xi + (size_t)s1 * DIM + co);
        sum.x += a0.x + a1.x; sum.y += a0.y + a1.y;
        sum.z += a0.z + a1.z; sum.w += a0.w + a1.w;
        mx.x = fmaxf(mx.x, fmaxf(m0.x, m1.x)); mx.y = fmaxf(mx.y, fmaxf(m0.y, m1.y));
        mx.z = fmaxf(mx.z, fmaxf(m0.z, m1.z)); mx.w = fmaxf(mx.w, fmaxf(m0.w, m1.w));
    }
    if (e < deg) {
        const int s0 = __ldg(g_ssrc + beg + e);
        const float4 a0 = *reinterpret_cast<const float4*>(x    + (size_t)s0 * DIM + co);
        const float4 m0 = *reinterpret_cast<const float4*>(g_xi + (size_t)s0 * DIM + co);
        sum.x += a0.x; sum.y += a0.y; sum.z += a0.z; sum.w += a0.w;
        mx.x = fmaxf(mx.x, m0.x); mx.y = fmaxf(mx.y, m0.y);
        mx.z = fmaxf(mx.z, m0.z); mx.w = fmaxf(mx.w, m0.w);
    }
    if (deg == 0) mx = make_float4(0.f, 0.f, 0.f, 0.f);

    const size_t o = (size_t)w * DIM + co;
    uint32_t h0, l0, h1, l1;
    split2(sum.x, sum.y, h0, l0);
    split2(sum.z, sum.w, h1, l1);
    *reinterpret_cast<uint2*>(g_ash + o) = make_uint2(h0, h1);
    *reinterpret_cast<uint2*>(g_asl + o) = make_uint2(l0, l1);
    split2(mx.x, mx.y, h0, l0);
    split2(mx.z, mx.w, h1, l1);
    *reinterpret_cast<uint2*>(g_amh + o) = make_uint2(h0, h1);
    *reinterpret_cast<uint2*>(g_aml + o) = make_uint2(l0, l1);
}

// ---------------- GRU elementwise (2 elems/thread), writes rnn hi/lo ----------------
__global__ void gru_kernel(const float* __restrict__ x, int M) {
    const size_t p = (size_t)blockIdx.x * blockDim.x + threadIdx.x;
    if (p >= (size_t)M * DIM / 2) return;
    const size_t i = p * 2;
    const size_t m = i >> 7;
    const int    d = (int)(i & 127);
    const size_t b = m * (3 * DIM);
    const float2 ir = *reinterpret_cast<const float2*>(g_gi + b + d);
    const float2 hr = *reinterpret_cast<const float2*>(g_gh + b + d);
    const float2 iz = *reinterpret_cast<const float2*>(g_gi + b + DIM + d);
    const float2 hz = *reinterpret_cast<const float2*>(g_gh + b + DIM + d);
    const float2 in = *reinterpret_cast<const float2*>(g_gi + b + 2*DIM + d);
    const float2 hn = *reinterpret_cast<const float2*>(g_gh + b + 2*DIM + d);
    const float2 xv = *reinterpret_cast<const float2*>(x + i);
    const float r0 = 1.f / (1.f + __expf(-(ir.x + hr.x)));
    const float r1 = 1.f / (1.f + __expf(-(ir.y + hr.y)));
    const float z0 = 1.f / (1.f + __expf(-(iz.x + hz.x)));
    const float z1 = 1.f / (1.f + __expf(-(iz.y + hz.y)));
    const float n0 = tanhf(in.x + r0 * hn.x);
    const float n1 = tanhf(in.y + r1 * hn.y);
    const float v0 = (1.f - z0) * n0 + z0 * xv.x;
    const float v1 = (1.f - z1) * n1 + z1 * xv.y;
    uint32_t hi, lo;
    split2(v0, v1, hi, lo);
    *reinterpret_cast<uint32_t*>(g_rnh + i) = hi;
    *reinterpret_cast<uint32_t*>(g_rnl + i) = lo;
}

// ---------------- batchnorm: finalize + apply fused (float4 per thread) ----------------
__global__ void bn_apply(const float* __restrict__ gamma, const float* __restrict__ beta,
                         float* __restrict__ out, size_t n4, float invM) {
    __shared__ float ssc[128], ssh[128];
    if (threadIdx.x < 128) {
        const int c = threadIdx.x;
        const float mean = g_stats[c] * invM;
        const float var  = g_stats[128 + c] * invM - mean * mean;
        const float sc   = gamma[c] * rsqrtf(var + 1e-5f);
        ssc[c] = sc;
        ssh[c] = beta[c] - mean * sc;
    }
    __syncthreads();
    const size_t i = (size_t)blockIdx.x * blockDim.x + threadIdx.x;
    if (i >= n4) return;
    const int c = (int)((i * 4) & 127);
    float4 v = *reinterpret_cast<float4*>(out + i * 4);
    v.x = v.x * ssc[c + 0] + ssh[c + 0];
    v.y = v.y * ssc[c + 1] + ssh[c + 1];
    v.z = v.z * ssc[c + 2] + ssh[c + 2];
    v.w = v.w * ssc[c + 3] + ssh[c + 3];
    *reinterpret_cast<float4*>(out + i * 4) = v;
}

// ---------------- launcher ----------------
extern "C" void kernel_launch(void* const* d_in, const int* in_sizes, int n_in,
                              void* d_out, int out_size)
{
    const float* x       = (const float*)d_in[0];
    const int*   edges   = (const int*)  d_in[1];
    const float* W_aff   = (const float*)d_in[2];
    const float* b_aff   = (const float*)d_in[3];
    const float* W_ih    = (const float*)d_in[4];
    const float* b_ih    = (const float*)d_in[5];
    const float* W_hh    = (const float*)d_in[6];
    const float* b_hh    = (const float*)d_in[7];
    const float* W_merge = (const float*)d_in[8];
    const float* b_merge = (const float*)d_in[9];
    const float* epsp    = (const float*)d_in[10];
    const float* W1      = (const float*)d_in[11];
    const float* b1      = (const float*)d_in[12];
    const float* W2      = (const float*)d_in[13];
    const float* b2      = (const float*)d_in[14];
    const float* gamma   = (const float*)d_in[15];
    const float* beta    = (const float*)d_in[16];
    float* out = (float*)d_out;

    const int M = in_sizes[0] / DIM;
    const int E = in_sizes[1] / 2;
    const size_t ND = (size_t)M * DIM;

    void *pp;
    cudaGetSymbolAddress(&pp, g_xi);   float* xi = (float*)pp;
    cudaGetSymbolAddress(&pp, g_gi);   float* gi = (float*)pp;
    cudaGetSymbolAddress(&pp, g_gh);   float* gh = (float*)pp;
    cudaGetSymbolAddress(&pp, g_xh);   __nv_bfloat16* xh  = (__nv_bfloat16*)pp;
    cudaGetSymbolAddress(&pp, g_xl);   __nv_bfloat16* xl  = (__nv_bfloat16*)pp;
    cudaGetSymbolAddress(&pp, g_ash);  __nv_bfloat16* ash = (__nv_bfloat16*)pp;
    cudaGetSymbolAddress(&pp, g_asl);  __nv_bfloat16* asl = (__nv_bfloat16*)pp;
    cudaGetSymbolAddress(&pp, g_amh);  __nv_bfloat16* amh = (__nv_bfloat16*)pp;
    cudaGetSymbolAddress(&pp, g_aml);  __nv_bfloat16* aml = (__nv_bfloat16*)pp;
    cudaGetSymbolAddress(&pp, g_rnh);  __nv_bfloat16* rnh = (__nv_bfloat16*)pp;
    cudaGetSymbolAddress(&pp, g_rnl);  __nv_bfloat16* rnl = (__nv_bfloat16*)pp;
    cudaGetSymbolAddress(&pp, g_hh);   __nv_bfloat16* hh  = (__nv_bfloat16*)pp;
    cudaGetSymbolAddress(&pp, g_hl);   __nv_bfloat16* hl  = (__nv_bfloat16*)pp;
    cudaGetSymbolAddress(&pp, g_t1h);  __nv_bfloat16* t1h = (__nv_bfloat16*)pp;
    cudaGetSymbolAddress(&pp, g_t1l);  __nv_bfloat16* t1l = (__nv_bfloat16*)pp;
    cudaGetSymbolAddress(&pp, g_waffh); __nv_bfloat16* waffh = (__nv_bfloat16*)pp;
    cudaGetSymbolAddress(&pp, g_waffl); __nv_bfloat16* waffl = (__nv_bfloat16*)pp;
    cudaGetSymbolAddress(&pp, g_wihh);  __nv_bfloat16* wihh  = (__nv_bfloat16*)pp;
    cudaGetSymbolAddress(&pp, g_wihl);  __nv_bfloat16* wihl  = (__nv_bfloat16*)pp;
    cudaGetSymbolAddress(&pp, g_whhh);  __nv_bfloat16* whhh  = (__nv_bfloat16*)pp;
    cudaGetSymbolAddress(&pp, g_whhl);  __nv_bfloat16* whhl  = (__nv_bfloat16*)pp;
    cudaGetSymbolAddress(&pp, g_wmh);   __nv_bfloat16* wmh   = (__nv_bfloat16*)pp;
    cudaGetSymbolAddress(&pp, g_wml);   __nv_bfloat16* wml   = (__nv_bfloat16*)pp;
    cudaGetSymbolAddress(&pp, g_w1h);   __nv_bfloat16* w1h   = (__nv_bfloat16*)pp;
    cudaGetSymbolAddress(&pp, g_w1l);   __nv_bfloat16* w1l   = (__nv_bfloat16*)pp;
    cudaGetSymbolAddress(&pp, g_w2h);   __nv_bfloat16* w2h   = (__nv_bfloat16*)pp;
    cudaGetSymbolAddress(&pp, g_w2l);   __nv_bfloat16* w2l   = (__nv_bfloat16*)pp;

    cudaFuncSetAttribute(tc_gemm<false,true,false,false,false>, cudaFuncAttributeMaxDynamicSharedMemorySize, TCG_SMEM);
    cudaFuncSetAttribute(tc_gemm<false,true,true, true, false>, cudaFuncAttributeMaxDynamicSharedMemorySize, TCG_SMEM);
    cudaFuncSetAttribute(tc_gemm<true, true,false,true, false>, cudaFuncAttributeMaxDynamicSharedMemorySize, TCG_SMEM);
    cudaFuncSetAttribute(tc_gemm<true, true,false,false,true >, cudaFuncAttributeMaxDynamicSharedMemorySize, TCG_BNS);
    cudaFuncSetAttribute(tc_gemm_xigh, cudaFuncAttributeMaxDynamicSharedMemorySize, TCG_SMEM);

    const int mtiles = (M + 127) / 128;
    const int e_blk  = (E + 255) / 256;
    const int m_blk  = (M + 255) / 256;
    const int nscan  = (M + 511) / 512;

    // ---- CSR build (also zeroes bn stats) ----
    k_zero <<<m_blk, 256>>>(M);
    k_hist <<<e_blk, 256>>>(edges, E);
    k_scan1<<<nscan, 512>>>(M);
    k_scan2<<<1, 1024>>>(nscan);
    k_scan3<<<m_blk, 256>>>(M);
    k_place<<<e_blk, 256>>>(edges, E);

    // ---- single merged split: x + all 6 weights -> bf16 hi/lo ----
    {
        SplitJobs jobs;
        const float* srcs[7]       = {x, W_aff, W_ih, W_hh, W_merge, W1, W2};
        __nv_bfloat16* dhs[7]      = {xh, waffh, wihh, whhh, wmh, w1h, w2h};
        __nv_bfloat16* dls[7]      = {xl, waffl, wihl, whhl, wml, w1l, w2l};
        const int cnts[7]          = {(int)(ND / 4), 128*128/4, 384*128/4, 384*128/4,
                                      128*256/4, 256*128/4, 128*256/4};
        int acc = 0;
        for (int k = 0; k < 7; k++) {
            jobs.src[k] = srcs[k]; jobs.dh[k] = dhs[k]; jobs.dl[k] = dls[k];
            jobs.off[k] = acc; acc += cnts[k];
        }
        jobs.off[7] = acc;
        k_split_all<<<(acc + 255) / 256, 256>>>(jobs);
    }

    // ---- merged: xi = x @ W_aff^T + b_aff  AND  gh = x @ W_hh^T + b_hh ----
    tc_gemm_xigh<<<mtiles, 256, TCG_SMEM>>>(
        xh, xl, waffh, waffl, whhh, whhl, b_aff, b_hh, xi, gh, M);

    // ---- aggregate: sum(x[src]), max(xi[src]) -> hi/lo splits ----
    k_aggregate<<<(M + 7) / 8, 256>>>(x, M);

    // ---- gi = agg_max @ W_ih^T + b_ih  (N=384, fp32) ----
    tc_gemm<false,true,false,false,false><<<mtiles, 256, TCG_SMEM>>>(
        amh, aml, nullptr, nullptr, DIM, wihh, wihl, DIM,
        b_ih, nullptr, nullptr, gi, nullptr, nullptr, 3*DIM, M, 1, 6);

    // ---- GRU -> rnn hi/lo ----
    gru_kernel<<<(int)((ND/2 + 255) / 256), 256>>>(x, M);

    // ---- h = [aggsum, rnn] @ W_merge^T + b_merge + eps*x  (K=256 fused, hi/lo out) ----
    tc_gemm<false,true,true,true,false><<<mtiles, 256, TCG_SMEM>>>(
        ash, asl, rnh, rnl, DIM, wmh, wml, 2*DIM,
        b_merge, x, epsp, nullptr, hh, hl, DIM, M, 2, 2);

    // ---- t1 = relu(h @ W1^T + b1)  (N=256, hi/lo out) ----
    tc_gemm<true,true,false,true,false><<<mtiles, 256, TCG_SMEM>>>(
        hh, hl, nullptr, nullptr, DIM, w1h, w1l, DIM,
        b1, nullptr, nullptr, nullptr, t1h, t1l, HID, M, 1, 4);

    // ---- out = relu(t1 @ W2^T + b2)  (K=256, fp32 out) + fused BN stats ----
    tc_gemm<true,true,false,false,true><<<mtiles, 256, TCG_BNS>>>(
        t1h, t1l, t1h + 128, t1l + 128, HID, w2h, w2l, 2*DIM,
        b2, nullptr, nullptr, out, nullptr, nullptr, DIM, M, 2, 2);

    // ---- batchnorm finalize + apply (fused) ----
    bn_apply<<<(int)((ND/4 + 255) / 256), 256>>>(gamma, beta, out, ND / 4, 1.f / (float)M);
}

// round 15
// speedup vs baseline: 1.0124x; 1.0124x over previous
#include <cuda_runtime.h>
#include <cuda_bf16.h>
#include <cstdint>
#include <math.h>

// ---------------- problem constants ----------------
#define MAXN   100000
#define MROUND 100096      // MAXN rounded up to 128-row tiles
#define MAXE   1600000
#define DIM    128
#define HID    256

// ---------------- scratch (static device memory; no allocation) ----------------
__device__ __align__(128) float g_xi  [(size_t)MROUND * DIM];
__device__ __align__(128) float g_gi  [(size_t)MROUND * 3 * DIM];
__device__ __align__(128) float g_gh  [(size_t)MROUND * 3 * DIM];
__device__ __align__(128) float g_stats[1024];
__device__ __align__(128) __nv_bfloat16 g_xh [(size_t)MROUND * DIM];
__device__ __align__(128) __nv_bfloat16 g_xl [(size_t)MROUND * DIM];
__device__ __align__(128) __nv_bfloat16 g_ash[(size_t)MROUND * DIM];
__device__ __align__(128) __nv_bfloat16 g_asl[(size_t)MROUND * DIM];
__device__ __align__(128) __nv_bfloat16 g_amh[(size_t)MROUND * DIM];
__device__ __align__(128) __nv_bfloat16 g_aml[(size_t)MROUND * DIM];
__device__ __align__(128) __nv_bfloat16 g_rnh[(size_t)MROUND * DIM];
__device__ __align__(128) __nv_bfloat16 g_rnl[(size_t)MROUND * DIM];
__device__ __align__(128) __nv_bfloat16 g_hh [(size_t)MROUND * DIM];
__device__ __align__(128) __nv_bfloat16 g_hl [(size_t)MROUND * DIM];
__device__ __align__(128) __nv_bfloat16 g_t1h[(size_t)MROUND * HID];
__device__ __align__(128) __nv_bfloat16 g_t1l[(size_t)MROUND * HID];
__device__ __align__(128) __nv_bfloat16 g_waffh[128*128], g_waffl[128*128];
__device__ __align__(128) __nv_bfloat16 g_wihh [384*128], g_wihl [384*128];
__device__ __align__(128) __nv_bfloat16 g_whhh [384*128], g_whhl [384*128];
__device__ __align__(128) __nv_bfloat16 g_wmh  [128*256], g_wml  [128*256];
__device__ __align__(128) __nv_bfloat16 g_w1h  [256*128], g_w1l  [256*128];
__device__ __align__(128) __nv_bfloat16 g_w2h  [128*256], g_w2l  [128*256];
__device__ __align__(128) int g_deg [MAXN];
__device__ __align__(128) int g_off [MAXN];
__device__ __align__(128) int g_cur [MAXN];
__device__ __align__(128) int g_part[1024];
__device__ __align__(128) int g_ssrc[MAXE];

// ================= helpers =================
__device__ __forceinline__ uint32_t smem_u32(const void* p) {
    uint32_t a;
    asm("{ .reg .u64 t; cvta.to.shared.u64 t, %1; cvt.u32.u64 %0, t; }" : "=r"(a) : "l"(p));
    return a;
}
__device__ __forceinline__ void ldsm_x4(uint32_t& r0, uint32_t& r1, uint32_t& r2, uint32_t& r3,
                                        uint32_t addr) {
    asm volatile("ldmatrix.sync.aligned.m8n8.x4.shared.b16 {%0,%1,%2,%3}, [%4];"
                 : "=r"(r0), "=r"(r1), "=r"(r2), "=r"(r3) : "r"(addr));
}
__device__ __forceinline__ void mma_bf16(float* c, const uint32_t* a, uint32_t b0, uint32_t b1) {
    asm volatile(
        "mma.sync.aligned.m16n8k16.row.col.f32.bf16.bf16.f32 "
        "{%0,%1,%2,%3}, {%4,%5,%6,%7}, {%8,%9}, {%0,%1,%2,%3};"
        : "+f"(c[0]), "+f"(c[1]), "+f"(c[2]), "+f"(c[3])
        : "r"(a[0]), "r"(a[1]), "r"(a[2]), "r"(a[3]), "r"(b0), "r"(b1));
}
__device__ __forceinline__ void split2(float vx, float vy, uint32_t& hi, uint32_t& lo) {
    __nv_bfloat162 h = __floats2bfloat162_rn(vx, vy);
    float rx = vx - __bfloat162float(h.x);
    float ry = vy - __bfloat162float(h.y);
    __nv_bfloat162 l = __floats2bfloat162_rn(rx, ry);
    hi = *reinterpret_cast<const uint32_t*>(&h);
    lo = *reinterpret_cast<const uint32_t*>(&l);
}

// ---------------- smem layout ----------------
#define SROW      136
#define ATILE_B   (128 * SROW * 2)
#define WTILE_B   (64  * SROW * 2)
#define OFF_AHI   0
#define OFF_ALO   (ATILE_B)
#define OFF_WHI   (2 * ATILE_B)
#define OFF_WLO   (2 * ATILE_B + WTILE_B)
#define TCG_SMEM  (2 * ATILE_B + 2 * WTILE_B)   // 104448 -> 2 CTAs/SM
#define TCG_BNS   (TCG_SMEM + 1024)             // +256 floats of BN accumulators

// ================= GEMM core building blocks =================
struct MmaCtx {
    uint32_t sb;
    uint32_t aRowPart, bRowPart;
    int tid, wid, lane, bm, wm, wn, qr, qc;
};
__device__ __forceinline__ MmaCtx make_ctx(const char* smem) {
    MmaCtx c;
    c.sb   = smem_u32(smem);
    c.tid  = threadIdx.x;
    c.wid  = c.tid >> 5;
    c.lane = c.tid & 31;
    c.bm   = blockIdx.x * 128;
    c.wm   = (c.wid >> 1) * 32;
    c.wn   = (c.wid & 1) * 32;
    const int g  = c.lane >> 3;
    const int lr = c.lane & 7;
    c.aRowPart = (uint32_t)((c.wm + (g & 1) * 8 + lr) * SROW + (g >> 1) * 8);
    c.bRowPart = (uint32_t)((c.wn + (g >> 1) * 8 + lr) * SROW + (g & 1) * 8);
    c.qr = c.lane >> 2;
    c.qc = (c.lane & 3) * 2;
    return c;
}
__device__ __forceinline__ void load_A(char* smem, const MmaCtx& c,
                                       const __nv_bfloat16* ah, const __nv_bfloat16* al, int lda) {
#pragma unroll 4
    for (int it = c.tid; it < 2048; it += 256) {
        const int r = it >> 4;
        const int cc = (it & 15) * 8;
        const uint32_t off = (uint32_t)(r * SROW + cc) * 2;
        const size_t ga = (size_t)(c.bm + r) * lda + cc;
        *reinterpret_cast<uint4*>(smem + OFF_AHI + off) = *reinterpret_cast<const uint4*>(ah + ga);
        *reinterpret_cast<uint4*>(smem + OFF_ALO + off) = *reinterpret_cast<const uint4*>(al + ga);
    }
}
__device__ __forceinline__ void load_W(char* smem, const MmaCtx& c,
                                       const __nv_bfloat16* wh, const __nv_bfloat16* wl,
                                       int ldw, int rowbase, int kofs) {
#pragma unroll 2
    for (int it = c.tid; it < 1024; it += 256) {
        const int r = it >> 4;
        const int cc = (it & 15) * 8;
        const uint32_t off = (uint32_t)(r * SROW + cc) * 2;
        const size_t gw = (size_t)(rowbase + r) * ldw + kofs + cc;
        *reinterpret_cast<uint4*>(smem + OFF_WHI + off) = *reinterpret_cast<const uint4*>(wh + gw);
        *reinterpret_cast<uint4*>(smem + OFF_WLO + off) = *reinterpret_cast<const uint4*>(wl + gw);
    }
}
__device__ __forceinline__ void mma_chunk(const MmaCtx& c, float acc[2][4][4]) {
#pragma unroll
    for (int ks = 0; ks < 8; ks++) {
        const uint32_t kk = ks * 16;
        uint32_t ah_[2][4], al_[2][4];
        uint32_t bh_[4][2], bl_[4][2];
#pragma unroll
        for (int i = 0; i < 2; i++) {
            const uint32_t ao = (c.aRowPart + (uint32_t)(i * 16) * SROW + kk) * 2;
            ldsm_x4(ah_[i][0], ah_[i][1], ah_[i][2], ah_[i][3], c.sb + OFF_AHI + ao);
            ldsm_x4(al_[i][0], al_[i][1], al_[i][2], al_[i][3], c.sb + OFF_ALO + ao);
        }
        {
            const uint32_t bo0 = (c.bRowPart + kk) * 2;
            const uint32_t bo1 = (c.bRowPart + (uint32_t)(16 * SROW) + kk) * 2;
            ldsm_x4(bh_[0][0], bh_[0][1], bh_[1][0], bh_[1][1], c.sb + OFF_WHI + bo0);
            ldsm_x4(bh_[2][0], bh_[2][1], bh_[3][0], bh_[3][1], c.sb + OFF_WHI + bo1);
            ldsm_x4(bl_[0][0], bl_[0][1], bl_[1][0], bl_[1][1], c.sb + OFF_WLO + bo0);
            ldsm_x4(bl_[2][0], bl_[2][1], bl_[3][0], bl_[3][1], c.sb + OFF_WLO + bo1);
        }
#pragma unroll
        for (int i = 0; i < 2; i++)
#pragma unroll
            for (int j = 0; j < 4; j++) {
                mma_bf16(acc[i][j], ah_[i], bh_[j][0], bh_[j][1]);
                mma_bf16(acc[i][j], ah_[i], bl_[j][0], bl_[j][1]);
                mma_bf16(acc[i][j], al_[i], bh_[j][0], bh_[j][1]);
            }
    }
}

// ---------------- generic tensor GEMM (split-bf16, fp32 acc) ----------------
template<bool RELU, bool BIAS, bool EXTRA, bool OUTHL, bool BNS>
__global__ __launch_bounds__(256, 2)
void tc_gemm(const __nv_bfloat16* __restrict__ a0h, const __nv_bfloat16* __restrict__ a0l,
             const __nv_bfloat16* __restrict__ a1h, const __nv_bfloat16* __restrict__ a1l,
             int lda,
             const __nv_bfloat16* __restrict__ wh, const __nv_bfloat16* __restrict__ wl,
             int ldw,
             const float* __restrict__ bias, const float* __restrict__ extra,
             const float* __restrict__ epsp,
             float* __restrict__ Cf,
             __nv_bfloat16* __restrict__ Chh, __nv_bfloat16* __restrict__ Cll,
             int ldc, int M, int KC, int NYT)
{
    extern __shared__ char smem[];
    const MmaCtx c = make_ctx(smem);
    float* sacc = reinterpret_cast<float*>(smem + TCG_SMEM);
    if (BNS && c.tid < 256) sacc[c.tid] = 0.f;

    const float epsv = EXTRA ? __ldg(epsp) : 0.f;

    for (int ny = 0; ny < NYT; ny++) {
        float acc[2][4][4];
#pragma unroll
        for (int i = 0; i < 2; i++)
#pragma unroll
            for (int j = 0; j < 4; j++)
#pragma unroll
                for (int f = 0; f < 4; f++) acc[i][j][f] = 0.f;

        for (int kc = 0; kc < KC; kc++) {
            if (ny || kc) __syncthreads();
            if (KC > 1 || ny == 0)
                load_A(smem, c, kc ? a1h : a0h, kc ? a1l : a0l, lda);
            load_W(smem, c, wh, wl, ldw, ny * 64, kc * 128);
            __syncthreads();
            mma_chunk(c, acc);
        }

        // ---- epilogue (j-outer so BN partial sums reduce in registers) ----
#pragma unroll
        for (int j = 0; j < 4; j++) {
            const int col = ny * 64 + c.wn + j * 8 + c.qc;
            float bsx = 0.f, bsy = 0.f, bqx = 0.f, bqy = 0.f;
#pragma unroll
            for (int i = 0; i < 2; i++) {
#pragma unroll
                for (int half = 0; half < 2; half++) {
                    const int rr = c.bm + c.wm + i * 16 + c.qr + half * 8;
                    if (rr < M) {
                        float vx = acc[i][j][half * 2 + 0];
                        float vy = acc[i][j][half * 2 + 1];
                        if (BIAS) {
                            const float2 b2 = *reinterpret_cast<const float2*>(bias + col);
                            vx += b2.x; vy += b2.y;
                        }
                        if (EXTRA) {
                            const float2 e2 = *reinterpret_cast<const float2*>(extra + (size_t)rr * ldc + col);
                            vx = fmaf(epsv, e2.x, vx); vy = fmaf(epsv, e2.y, vy);
                        }
                        if (RELU) { vx = fmaxf(vx, 0.f); vy = fmaxf(vy, 0.f); }
                        if (OUTHL) {
                            uint32_t hi, lo;
                            split2(vx, vy, hi, lo);
                            *reinterpret_cast<uint32_t*>(Chh + (size_t)rr * ldc + col) = hi;
                            *reinterpret_cast<uint32_t*>(Cll + (size_t)rr * ldc + col) = lo;
                        } else {
                            *reinterpret_cast<float2*>(Cf + (size_t)rr * ldc + col) = make_float2(vx, vy);
                        }
                        if (BNS) {
                            bsx += vx; bsy += vy;
                            bqx = fmaf(vx, vx, bqx); bqy = fmaf(vy, vy, bqy);
                        }
                    }
                }
            }
            if (BNS) {
                atomicAdd(&sacc[col],           bsx);
                atomicAdd(&sacc[col + 1],       bsy);
                atomicAdd(&sacc[128 + col],     bqx);
                atomicAdd(&sacc[128 + col + 1], bqy);
            }
        }
    }

    if (BNS) {
        __syncthreads();
        if (c.tid < 128) {
            atomicAdd(&g_stats[c.tid],       sacc[c.tid]);
            atomicAdd(&g_stats[128 + c.tid], sacc[128 + c.tid]);
        }
    }
}

// ---------------- dual-job N=384 GEMM: y=0 -> gi (A=aggmax), y=1 -> gh (A=x) ----------------
__global__ __launch_bounds__(256, 2)
void tc_gemm_gigh(const __nv_bfloat16* __restrict__ amh, const __nv_bfloat16* __restrict__ aml,
                  const __nv_bfloat16* __restrict__ wihh, const __nv_bfloat16* __restrict__ wihl,
                  const float* __restrict__ b_ih, float* __restrict__ gi,
                  const __nv_bfloat16* __restrict__ xh, const __nv_bfloat16* __restrict__ xl,
                  const __nv_bfloat16* __restrict__ whhh, const __nv_bfloat16* __restrict__ whhl,
                  const float* __restrict__ b_hh, float* __restrict__ gh, int M)
{
    extern __shared__ char smem[];
    const MmaCtx c = make_ctx(smem);
    const bool isGi = (blockIdx.y == 0);
    const __nv_bfloat16* ah = isGi ? amh : xh;
    const __nv_bfloat16* al = isGi ? aml : xl;
    const __nv_bfloat16* wh = isGi ? wihh : whhh;
    const __nv_bfloat16* wl = isGi ? wihl : whhl;
    const float* bias = isGi ? b_ih : b_hh;
    float* Cf = isGi ? gi : gh;

    for (int ny = 0; ny < 6; ny++) {
        float acc[2][4][4];
#pragma unroll
        for (int i = 0; i < 2; i++)
#pragma unroll
            for (int j = 0; j < 4; j++)
#pragma unroll
                for (int f = 0; f < 4; f++) acc[i][j][f] = 0.f;

        if (ny) __syncthreads();
        if (ny == 0) load_A(smem, c, ah, al, DIM);
        load_W(smem, c, wh, wl, DIM, ny * 64, 0);
        __syncthreads();
        mma_chunk(c, acc);

#pragma unroll
        for (int j = 0; j < 4; j++) {
            const int col = ny * 64 + c.wn + j * 8 + c.qc;
#pragma unroll
            for (int i = 0; i < 2; i++) {
#pragma unroll
                for (int half = 0; half < 2; half++) {
                    const int rr = c.bm + c.wm + i * 16 + c.qr + half * 8;
                    if (rr < M) {
                        const float2 b2 = *reinterpret_cast<const float2*>(bias + col);
                        *reinterpret_cast<float2*>(Cf + (size_t)rr * 384 + col) =
                            make_float2(acc[i][j][half * 2 + 0] + b2.x,
                                        acc[i][j][half * 2 + 1] + b2.y);
                    }
                }
            }
        }
    }
}

// ================= merged split kernel: all fp32 -> bf16 hi/lo regions =================
struct SplitJobs {
    const float* src[7];
    __nv_bfloat16* dh[7];
    __nv_bfloat16* dl[7];
    int off[8];
};

__global__ void k_split_all(SplitJobs jobs) {
    const int i = blockIdx.x * blockDim.x + threadIdx.x;
    if (i >= jobs.off[7]) return;
    int r = 0;
#pragma unroll
    for (int k = 1; k < 7; k++) r += (i >= jobs.off[k]);
    const int li = i - jobs.off[r];
    const float4 v = *reinterpret_cast<const float4*>(jobs.src[r] + (size_t)li * 4);
    uint32_t h0, l0, h1, l1;
    split2(v.x, v.y, h0, l0);
    split2(v.z, v.w, h1, l1);
    *reinterpret_cast<uint2*>(jobs.dh[r] + (size_t)li * 4) = make_uint2(h0, h1);
    *reinterpret_cast<uint2*>(jobs.dl[r] + (size_t)li * 4) = make_uint2(l0, l1);
}

// ================= CSR build =================
__global__ void k_zero(int M) {
    int i = blockIdx.x * blockDim.x + threadIdx.x;
    if (i < M) g_deg[i] = 0;
    if (i < 1024) g_stats[i] = 0.f;
}
__global__ void k_hist(const int* __restrict__ edges, int E) {
    int i = blockIdx.x * blockDim.x + threadIdx.x;
    if (i < E) atomicAdd(&g_deg[__ldg(edges + E + i)], 1);
}
__global__ void k_scan1(int M) {
    __shared__ int s[512];
    const int tid = threadIdx.x;
    const int i = blockIdx.x * 512 + tid;
    const int v = (i < M) ? g_deg[i] : 0;
    s[tid] = v;
    __syncthreads();
#pragma unroll
    for (int d = 1; d < 512; d <<= 1) {
        int u = (tid >= d) ? s[tid - d] : 0;
        __syncthreads();
        s[tid] += u;
        __syncthreads();
    }
    if (i < M) g_off[i] = s[tid] - v;
    if (tid == 511) g_part[blockIdx.x] = s[511];
}
__global__ void k_scan2(int nblk) {
    __shared__ int s[1024];
    const int t = threadIdx.x;
    const int v = (t < nblk) ? g_part[t] : 0;
    s[t] = v;
    __syncthreads();
#pragma unroll
    for (int d = 1; d < 1024; d <<= 1) {
        int u = (t >= d) ? s[t - d] : 0;
        __syncthreads();
        s[t] += u;
        __syncthreads();
    }
    if (t < nblk) g_part[t] = s[t] - v;
}
__global__ void k_scan3(int M) {
    int i = blockIdx.x * blockDim.x + threadIdx.x;
    if (i < M) {
        int o = g_off[i] + g_part[i >> 9];
        g_off[i] = o;
        g_cur[i] = o;
    }
}
__global__ void k_place(const int* __restrict__ edges, int E) {
    int i = blockIdx.x * blockDim.x + threadIdx.x;
    if (i < E) {
        const int s = __ldg(edges + i);
        const int d = __ldg(edges + E + i);
        const int pos = atomicAdd(&g_cur[d], 1);
        g_ssrc[pos] = s;
    }
}

// ================= aggregation: warp per node, 2-edge unroll, no atomics =================
__global__ __launch_bounds__(256)
void k_aggregate(const float* __restrict__ x, int M)
{
    const int w = blockIdx.x * 8 + (threadIdx.x >> 5);
    const int lane = threadIdx.x & 31;
    if (w >= M) return;
    const int beg = g_off[w];
    const int deg = g_deg[w];
    const int co = lane * 4;

    float4 sum = make_float4(0.f, 0.f, 0.f, 0.f);
    float4 mx  = make_float4(-INFINITY, -INFINITY, -INFINITY, -INFINITY);

    int e = 0;
    for (; e + 2 <= deg; e += 2) {
        const int s0 = __ldg(g_ssrc + beg + e);
        const int s1 = __ldg(g_ssrc + beg + e + 1);
        const float4 a0 = *reinterpret_cast<const float4*>(x    + (size_t)s0 * DIM + co);
        const float4 m0 = *reinterpret_cast<const float4*>(g_xi + (size_t)s0 * DIM + co);
        const float4 a1 = *reinterpret_cast<const float4*>(x    + (size_t)s1 * DIM + co);
        const float4 m1 = *reinterpret_cast<const float4*>(g_xi + (size_t)s1 * DIM + co);
        sum.x += a0.x + a1.x; sum.y += a0.y + a1.y;
        sum.z += a0.z + a1.z; sum.w += a0.w + a1.w;
        mx.x = fmaxf(mx.x, fmaxf(m0.x, m1.x)); mx.y = fmaxf(mx.y, fmaxf(m0.y, m1.y));
        mx.z = fmaxf(mx.z, fmaxf(m0.z, m1.z)); mx.w = fmaxf(mx.w, fmaxf(m0.w, m1.w));
    }
    if (e < deg) {
        const int s0 = __ldg(g_ssrc + beg + e);
        const float4 a0 = *reinterpret_cast<const float4*>(x    + (size_t)s0 * DIM + co);
        const float4 m0 = *reinterpret_cast<const float4*>(g_xi + (size_t)s0 * DIM + co);
        sum.x += a0.x; sum.y += a0.y; sum.z += a0.z; sum.w += a0.w;
        mx.x = fmaxf(mx.x, m0.x); mx.y = fmaxf(mx.y, m0.y);
        mx.z = fmaxf(mx.z, m0.z); mx.w = fmaxf(mx.w, m0.w);
    }
    if (deg == 0) mx = make_float4(0.f, 0.f, 0.f, 0.f);

    const size_t o = (size_t)w * DIM + co;
    uint32_t h0, l0, h1, l1;
    split2(sum.x, sum.y, h0, l0);
    split2(sum.z, sum.w, h1, l1);
    *reinterpret_cast<uint2*>(g_ash + o) = make_uint2(h0, h1);
    *reinterpret_cast<uint2*>(g_asl + o) = make_uint2(l0, l1);
    split2(mx.x, mx.y, h0, l0);
    split2(mx.z, mx.w, h1, l1);
    *reinterpret_cast<uint2*>(g_amh + o) = make_uint2(h0, h1);
    *reinterpret_cast<uint2*>(g_aml + o) = make_uint2(l0, l1);
}

// ---------------- GRU elementwise (2 elems/thread), writes rnn hi/lo ----------------
__global__ void gru_kernel(const float* __restrict__ x, int M) {
    const size_t p = (size_t)blockIdx.x * blockDim.x + threadIdx.x;
    if (p >= (size_t)M * DIM / 2) return;
    const size_t i = p * 2;
    const size_t m = i >> 7;
    const int    d = (int)(i & 127);
    const size_t b = m * (3 * DIM);
    const float2 ir = *reinterpret_cast<const float2*>(g_gi + b + d);
    const float2 hr = *reinterpret_cast<const float2*>(g_gh + b + d);
    const float2 iz = *reinterpret_cast<const float2*>(g_gi + b + DIM + d);
    const float2 hz = *reinterpret_cast<const float2*>(g_gh + b + DIM + d);
    const float2 in = *reinterpret_cast<const float2*>(g_gi + b + 2*DIM + d);
    const float2 hn = *reinterpret_cast<const float2*>(g_gh + b + 2*DIM + d);
    const float2 xv = *reinterpret_cast<const float2*>(x + i);
    const float r0 = 1.f / (1.f + __expf(-(ir.x + hr.x)));
    const float r1 = 1.f / (1.f + __expf(-(ir.y + hr.y)));
    const float z0 = 1.f / (1.f + __expf(-(iz.x + hz.x)));
    const float z1 = 1.f / (1.f + __expf(-(iz.y + hz.y)));
    const float n0 = tanhf(in.x + r0 * hn.x);
    const float n1 = tanhf(in.y + r1 * hn.y);
    const float v0 = (1.f - z0) * n0 + z0 * xv.x;
    const float v1 = (1.f - z1) * n1 + z1 * xv.y;
    uint32_t hi, lo;
    split2(v0, v1, hi, lo);
    *reinterpret_cast<uint32_t*>(g_rnh + i) = hi;
    *reinterpret_cast<uint32_t*>(g_rnl + i) = lo;
}

// ---------------- batchnorm: finalize + apply fused (float4 per thread) ----------------
__global__ void bn_apply(const float* __restrict__ gamma, const float* __restrict__ beta,
                         float* __restrict__ out, size_t n4, float invM) {
    __shared__ float ssc[128], ssh[128];
    if (threadIdx.x < 128) {
        const int c = threadIdx.x;
        const float mean = g_stats[c] * invM;
        const float var  = g_stats[128 + c] * invM - mean * mean;
        const float sc   = gamma[c] * rsqrtf(var + 1e-5f);
        ssc[c] = sc;
        ssh[c] = beta[c] - mean * sc;
    }
    __syncthreads();
    const size_t i = (size_t)blockIdx.x * blockDim.x + threadIdx.x;
    if (i >= n4) return;
    const int c = (int)((i * 4) & 127);
    float4 v = *reinterpret_cast<float4*>(out + i * 4);
    v.x = v.x * ssc[c + 0] + ssh[c + 0];
    v.y = v.y * ssc[c + 1] + ssh[c + 1];
    v.z = v.z * ssc[c + 2] + ssh[c + 2];
    v.w = v.w * ssc[c + 3] + ssh[c + 3];
    *reinterpret_cast<float4*>(out + i * 4) = v;
}

// ---------------- launcher ----------------
extern "C" void kernel_launch(void* const* d_in, const int* in_sizes, int n_in,
                              void* d_out, int out_size)
{
    const float* x       = (const float*)d_in[0];
    const int*   edges   = (const int*)  d_in[1];
    const float* W_aff   = (const float*)d_in[2];
    const float* b_aff   = (const float*)d_in[3];
    const float* W_ih    = (const float*)d_in[4];
    const float* b_ih    = (const float*)d_in[5];
    const float* W_hh    = (const float*)d_in[6];
    const float* b_hh    = (const float*)d_in[7];
    const float* W_merge = (const float*)d_in[8];
    const float* b_merge = (const float*)d_in[9];
    const float* epsp    = (const float*)d_in[10];
    const float* W1      = (const float*)d_in[11];
    const float* b1      = (const float*)d_in[12];
    const float* W2      = (const float*)d_in[13];
    const float* b2      = (const float*)d_in[14];
    const float* gamma   = (const float*)d_in[15];
    const float* beta    = (const float*)d_in[16];
    float* out = (float*)d_out;

    const int M = in_sizes[0] / DIM;
    const int E = in_sizes[1] / 2;
    const size_t ND = (size_t)M * DIM;

    void *pp;
    cudaGetSymbolAddress(&pp, g_xi);   float* xi = (float*)pp;
    cudaGetSymbolAddress(&pp, g_gi);   float* gi = (float*)pp;
    cudaGetSymbolAddress(&pp, g_gh);   float* gh = (float*)pp;
    cudaGetSymbolAddress(&pp, g_xh);   __nv_bfloat16* xh  = (__nv_bfloat16*)pp;
    cudaGetSymbolAddress(&pp, g_xl);   __nv_bfloat16* xl  = (__nv_bfloat16*)pp;
    cudaGetSymbolAddress(&pp, g_ash);  __nv_bfloat16* ash = (__nv_bfloat16*)pp;
    cudaGetSymbolAddress(&pp, g_asl);  __nv_bfloat16* asl = (__nv_bfloat16*)pp;
    cudaGetSymbolAddress(&pp, g_amh);  __nv_bfloat16* amh = (__nv_bfloat16*)pp;
    cudaGetSymbolAddress(&pp, g_aml);  __nv_bfloat16* aml = (__nv_bfloat16*)pp;
    cudaGetSymbolAddress(&pp, g_rnh);  __nv_bfloat16* rnh = (__nv_bfloat16*)pp;
    cudaGetSymbolAddress(&pp, g_rnl);  __nv_bfloat16* rnl = (__nv_bfloat16*)pp;
    cudaGetSymbolAddress(&pp, g_hh);   __nv_bfloat16* hh  = (__nv_bfloat16*)pp;
    cudaGetSymbolAddress(&pp, g_hl);   __nv_bfloat16* hl  = (__nv_bfloat16*)pp;
    cudaGetSymbolAddress(&pp, g_t1h);  __nv_bfloat16* t1h = (__nv_bfloat16*)pp;
    cudaGetSymbolAddress(&pp, g_t1l);  __nv_bfloat16* t1l = (__nv_bfloat16*)pp;
    cudaGetSymbolAddress(&pp, g_waffh); __nv_bfloat16* waffh = (__nv_bfloat16*)pp;
    cudaGetSymbolAddress(&pp, g_waffl); __nv_bfloat16* waffl = (__nv_bfloat16*)pp;
    cudaGetSymbolAddress(&pp, g_wihh);  __nv_bfloat16* wihh  = (__nv_bfloat16*)pp;
    cudaGetSymbolAddress(&pp, g_wihl);  __nv_bfloat16* wihl  = (__nv_bfloat16*)pp;
    cudaGetSymbolAddress(&pp, g_whhh);  __nv_bfloat16* whhh  = (__nv_bfloat16*)pp;
    cudaGetSymbolAddress(&pp, g_whhl);  __nv_bfloat16* whhl  = (__nv_bfloat16*)pp;
    cudaGetSymbolAddress(&pp, g_wmh);   __nv_bfloat16* wmh   = (__nv_bfloat16*)pp;
    cudaGetSymbolAddress(&pp, g_wml);   __nv_bfloat16* wml   = (__nv_bfloat16*)pp;
    cudaGetSymbolAddress(&pp, g_w1h);   __nv_bfloat16* w1h   = (__nv_bfloat16*)pp;
    cudaGetSymbolAddress(&pp, g_w1l);   __nv_bfloat16* w1l   = (__nv_bfloat16*)pp;
    cudaGetSymbolAddress(&pp, g_w2h);   __nv_bfloat16* w2h   = (__nv_bfloat16*)pp;
    cudaGetSymbolAddress(&pp, g_w2l);   __nv_bfloat16* w2l   = (__nv_bfloat16*)pp;

    cudaFuncSetAttribute(tc_gemm<false,true,false,false,false>, cudaFuncAttributeMaxDynamicSharedMemorySize, TCG_SMEM);
    cudaFuncSetAttribute(tc_gemm<false,true,true, true, false>, cudaFuncAttributeMaxDynamicSharedMemorySize, TCG_SMEM);
    cudaFuncSetAttribute(tc_gemm<true, true,false,true, false>, cudaFuncAttributeMaxDynamicSharedMemorySize, TCG_SMEM);
    cudaFuncSetAttribute(tc_gemm<true, true,false,false,true >, cudaFuncAttributeMaxDynamicSharedMemorySize, TCG_BNS);
    cudaFuncSetAttribute(tc_gemm_gigh, cudaFuncAttributeMaxDynamicSharedMemorySize, TCG_SMEM);

    const int mtiles = (M + 127) / 128;
    const int e_blk  = (E + 255) / 256;
    const int m_blk  = (M + 255) / 256;
    const int nscan  = (M + 511) / 512;

    // ---- CSR build (also zeroes bn stats) ----
    k_zero <<<m_blk, 256>>>(M);
    k_hist <<<e_blk, 256>>>(edges, E);
    k_scan1<<<nscan, 512>>>(M);
    k_scan2<<<1, 1024>>>(nscan);
    k_scan3<<<m_blk, 256>>>(M);
    k_place<<<e_blk, 256>>>(edges, E);

    // ---- single merged split: x + all 6 weights -> bf16 hi/lo ----
    {
        SplitJobs jobs;
        const float* srcs[7]       = {x, W_aff, W_ih, W_hh, W_merge, W1, W2};
        __nv_bfloat16* dhs[7]      = {xh, waffh, wihh, whhh, wmh, w1h, w2h};
        __nv_bfloat16* dls[7]      = {xl, waffl, wihl, whhl, wml, w1l, w2l};
        const int cnts[7]          = {(int)(ND / 4), 128*128/4, 384*128/4, 384*128/4,
                                      128*256/4, 256*128/4, 128*256/4};
        int acc = 0;
        for (int k = 0; k < 7; k++) {
            jobs.src[k] = srcs[k]; jobs.dh[k] = dhs[k]; jobs.dl[k] = dls[k];
            jobs.off[k] = acc; acc += cnts[k];
        }
        jobs.off[7] = acc;
        k_split_all<<<(acc + 255) / 256, 256>>>(jobs);
    }

    // ---- xi = x @ W_aff^T + b_aff ----
    tc_gemm<false,true,false,false,false><<<mtiles, 256, TCG_SMEM>>>(
        xh, xl, nullptr, nullptr, DIM, waffh, waffl, DIM,
        b_aff, nullptr, nullptr, xi, nullptr, nullptr, DIM, M, 1, 2);

    // ---- aggregate: sum(x[src]), max(xi[src]) -> hi/lo splits ----
    k_aggregate<<<(M + 7) / 8, 256>>>(x, M);

    // ---- dual-job: gi = aggmax @ W_ih^T + b_ih  AND  gh = x @ W_hh^T + b_hh ----
    tc_gemm_gigh<<<dim3(mtiles, 2), 256, TCG_SMEM>>>(
        amh, aml, wihh, wihl, b_ih, gi,
        xh, xl, whhh, whhl, b_hh, gh, M);

    // ---- GRU -> rnn hi/lo ----
    gru_kernel<<<(int)((ND/2 + 255) / 256), 256>>>(x, M);

    // ---- h = [aggsum, rnn] @ W_merge^T + b_merge + eps*x  (K=256 fused, hi/lo out) ----
    tc_gemm<false,true,true,true,false><<<mtiles, 256, TCG_SMEM>>>(
        ash, asl, rnh, rnl, DIM, wmh, wml, 2*DIM,
        b_merge, x, epsp, nullptr, hh, hl, DIM, M, 2, 2);

    // ---- t1 = relu(h @ W1^T + b1)  (N=256, hi/lo out) ----
    tc_gemm<true,true,false,true,false><<<mtiles, 256, TCG_SMEM>>>(
        hh, hl, nullptr, nullptr, DIM, w1h, w1l, DIM,
        b1, nullptr, nullptr, nullptr, t1h, t1l, HID, M, 1, 4);

    // ---- out = relu(t1 @ W2^T + b2)  (K=256, fp32 out) + fused BN stats ----
    tc_gemm<true,true,false,false,true><<<mtiles, 256, TCG_BNS>>>(
        t1h, t1l, t1h + 128, t1l + 128, HID, w2h, w2l, 2*DIM,
        b2, nullptr, nullptr, out, nullptr, nullptr, DIM, M, 2, 2);

    // ---- batchnorm finalize + apply (fused) ----
    bn_apply<<<(int)((ND/4 + 255) / 256), 256>>>(gamma, beta, out, ND / 4, 1.f / (float)M);
}